// round 15
// baseline (speedup 1.0000x reference)
#include <cuda_runtime.h>
#include <cstdint>

#define TT 4
#define BBATCH 32
#define CC 384
#define NN 196
#define MM 6272            // BBATCH*NN
#define HH 8
#define DD 48
#define DQKV 1152

typedef unsigned long long u64;
typedef unsigned int u32;

// packed f32x2 helpers (sm_103a FFMA2 only reachable via PTX)
#define FMA_F32X2(d, a, b) \
    asm("fma.rn.f32x2 %0, %1, %2, %3;" : "=l"(d) : "l"(a), "l"(b), "l"(d))
#define DUP_F32X2(d, f) \
    asm("mov.b64 %0, {%1, %1};" : "=l"(d) : "r"(__float_as_uint(f)))
#define UNPACK_F32X2(lo, hi, v) \
    asm("mov.b64 {%0, %1}, %2;" : "=r"(lo), "=r"(hi) : "l"(v))

__device__ __forceinline__ void cpasync16(void* dst, const void* src) {
    unsigned ds = (unsigned)__cvta_generic_to_shared(dst);
    asm volatile("cp.async.cg.shared.global [%0], [%1], 16;" :: "r"(ds), "l"(src));
}
#define CP_COMMIT() asm volatile("cp.async.commit_group;" ::: "memory")
#define CP_WAIT1()  asm volatile("cp.async.wait_group 1;" ::: "memory")

// ---------------- scratch (device globals; no allocation allowed) ----------------
__device__ __align__(16) unsigned char g_spk[TT*MM*DQKV];   // spike bytes (q|k|v)
__device__ __align__(16) float g_Xt[TT*CC*MM];              // x transposed to [t][c][m]
__device__ __align__(16) float g_attnspk[TT*CC*MM];         // attn-LIF spikes, [t][c][m]
__device__ __align__(16) float g_Wt1152[CC*DQKV];           // transposed qkv weights [C][1152]
__device__ __align__(16) float g_Wt384[CC*CC];              // transposed wp [C][384]

// ---------------- weight transpose prep ----------------
__global__ void k_prepw(const float* __restrict__ wq, const float* __restrict__ wk,
                        const float* __restrict__ wv, const float* __restrict__ wp) {
    int i = blockIdx.x * 256 + threadIdx.x;
    if (i < CC*DQKV) {
        int c = i / DQKV, dg = i - c*DQKV;
        int ten = dg / CC, d = dg - ten*CC;
        const float* w = (ten == 0) ? wq : (ten == 1) ? wk : wv;
        g_Wt1152[i] = w[d*CC + c];
    } else {
        int k = i - CC*DQKV;
        if (k < CC*CC) {
            int c = k / CC, d = k - c*CC;
            g_Wt384[k] = wp[d*CC + c];
        }
    }
}

// ---------------- X transpose: [t][b][c][n] -> [t][c][m] (m = b*NN+n) ----------------
__global__ void k_prepx(const float* __restrict__ x) {
    int i = blockIdx.x * 256 + threadIdx.x;            // i over TT*CC*MM
    int t = i / (CC*MM);
    int r = i - t*(CC*MM);
    int c = r / MM;
    int m = r - c*MM;
    int b = m / NN, n = m - b*NN;
    g_Xt[i] = x[(((size_t)t*BBATCH + b)*CC + c)*NN + n];
}

// ---------------- fused conv(1x1) + BN + LIF GEMM (FFMA2, cp.async, 512 thr) ----------------
// BM=64, BN=64, BK=16, 512 threads, 2m (one f32x2 pair) x 4d x 4t per thread.
// 32 regs of accumulator -> <=64 regs -> 2 blocks/SM -> 32 warps/SM for latency hiding.
// Strict sequential k-order per accumulator -> bit-identical outputs.
template<bool FINAL>
__global__ void __launch_bounds__(512, 2) k_conv_lif(
    const float* __restrict__ sc0, const float* __restrict__ sc1, const float* __restrict__ sc2,
    const float* __restrict__ bi0, const float* __restrict__ bi1, const float* __restrict__ bi2,
    float* __restrict__ outF)
{
    constexpr int DTOT = FINAL ? CC : DQKV;
    const float* __restrict__ A  = FINAL ? g_attnspk : g_Xt;
    const float* __restrict__ Wt = FINAL ? g_Wt384 : g_Wt1152;

    __shared__ __align__(16) float As[2][TT][16][64];   // 32 KB
    __shared__ __align__(16) float Ws[2][16][64];       //  8 KB

    const int tid = threadIdx.x;
    const int m0 = blockIdx.x * 64;
    const int d0 = blockIdx.y * 64;

    // acc2[t][j] : f32x2 pair over the thread's 2 consecutive m
    u64 acc2[TT][4];
    #pragma unroll
    for (int t = 0; t < TT; t++)
        #pragma unroll
        for (int j = 0; j < 4; j++) acc2[t][j] = 0ull;

    // stage loads: A = 64 rows (t*16+k) x 64 floats = 1024 x 16B; W = 16x64 = 256 x 16B
    auto issue = [&](int slot, int c0) {
        #pragma unroll
        for (int i = 0; i < 2; i++) {
            int e = tid + i*512;
            int row = e >> 4;           // 0..63
            int t = row >> 4, k = row & 15;
            int ch = (e & 15) * 4;
            cpasync16(&As[slot][t][k][ch],
                      A + ((size_t)t*CC + c0 + k)*MM + m0 + ch);
        }
        if (tid < 256) {
            int row = tid >> 4;         // 0..15
            int ch = (tid & 15) * 4;
            cpasync16(&Ws[slot][row][ch],
                      Wt + (size_t)(c0 + row)*DTOT + d0 + ch);
        }
    };

    // prologue: stages 0,1
    issue(0, 0);  CP_COMMIT();
    issue(1, 16); CP_COMMIT();

    const int tx4 = (tid & 15) * 4;     // d sub-tile
    const int ty2 = (tid >> 4) * 2;     // m sub-tile (pair base)

    for (int kt = 0; kt < 24; kt++) {
        CP_WAIT1();
        __syncthreads();
        const int buf = kt & 1;
        #pragma unroll
        for (int k = 0; k < 16; k++) {
            float4 bfv = *(const float4*)&Ws[buf][k][tx4];
            u64 b2[4];
            DUP_F32X2(b2[0], bfv.x);
            DUP_F32X2(b2[1], bfv.y);
            DUP_F32X2(b2[2], bfv.z);
            DUP_F32X2(b2[3], bfv.w);
            #pragma unroll
            for (int t = 0; t < TT; t++) {
                u64 av = *(const u64*)&As[buf][t][k][ty2];
                #pragma unroll
                for (int j = 0; j < 4; j++)
                    FMA_F32X2(acc2[t][j], av, b2[j]);
            }
        }
        __syncthreads();
        if (kt + 2 < 24) issue(buf, (kt + 2) * 16);
        CP_COMMIT();
    }

    // unpack: acc[t][i][j], i = m offset within pair
    float acc[TT][2][4];
    #pragma unroll
    for (int t = 0; t < TT; t++)
        #pragma unroll
        for (int j = 0; j < 4; j++) {
            u32 lo, hi;
            UNPACK_F32X2(lo, hi, acc2[t][j]);
            acc[t][0][j] = __uint_as_float(lo);
            acc[t][1][j] = __uint_as_float(hi);
        }

    // ---- epilogue: BN + LIF (exact reference op sequence; no fma contraction) ----
    int dl = d0 + tx4;
    const float *sc, *bi;
    if (FINAL) { sc = sc0; bi = bi0; }
    else {
        int ten = d0 / CC;
        dl = d0 - ten*CC + tx4;
        sc = (ten == 0) ? sc0 : (ten == 1) ? sc1 : sc2;
        bi = (ten == 0) ? bi0 : (ten == 1) ? bi1 : bi2;
    }
    float scv[4], biv[4];
    #pragma unroll
    for (int j = 0; j < 4; j++) { scv[j] = sc[dl + j]; biv[j] = bi[dl + j]; }

    if (!FINAL) {
        #pragma unroll
        for (int i = 0; i < 2; i++) {
            int m = m0 + ty2 + i;
            float v[4] = {0.f, 0.f, 0.f, 0.f};
            #pragma unroll
            for (int t = 0; t < TT; t++) {
                unsigned pk = 0;
                #pragma unroll
                for (int j = 0; j < 4; j++) {
                    float y = __fadd_rn(__fmul_rn(acc[t][i][j], scv[j]), biv[j]);
                    v[j] = __fadd_rn(v[j], __fmul_rn(__fadd_rn(y, -v[j]), 0.5f));
                    if (v[j] >= 1.0f) { pk |= 1u << (8*j); v[j] = 0.f; }
                }
                *(unsigned*)&g_spk[((size_t)t*MM + m)*DQKV + d0 + tx4] = pk;
            }
        }
    } else {
        // thread's 2 consecutive m never cross a batch boundary (NN even, ty2 even)
        const int mbase = m0 + ty2;
        const int b_o = mbase / NN;
        const int n0 = mbase - b_o*NN;          // 2-aligned
        float v[2][4];
        #pragma unroll
        for (int i = 0; i < 2; i++)
            #pragma unroll
            for (int j = 0; j < 4; j++) v[i][j] = 0.f;
        #pragma unroll
        for (int t = 0; t < TT; t++) {
            #pragma unroll
            for (int j = 0; j < 4; j++) {
                float2 o;
                float* ov = &o.x;
                #pragma unroll
                for (int i = 0; i < 2; i++) {
                    float y = __fadd_rn(__fmul_rn(acc[t][i][j], scv[j]), biv[j]);
                    v[i][j] = __fadd_rn(v[i][j], __fmul_rn(__fadd_rn(y, -v[i][j]), 0.5f));
                    bool hh = v[i][j] >= 1.0f;
                    ov[i] = hh ? 1.0f : 0.0f;
                    if (hh) v[i][j] = 0.f;
                }
                *(float2*)&outF[(((size_t)t*BBATCH + b_o)*CC + (dl + j))*NN + n0] = o;
            }
        }
    }
}

// ---------------- attention (pack fused, 512 threads): out = q @ (k^T v) * 0.125, LIF(0.5) ----
// Integer-exact: spikes binary, G entries <=196, sums <=9408 < 2^16.
// Phase 4 uses bit*word IMADs (fma pipe) to balance against the alu pipe.
// Output written in [t][c][m] layout for the projection conv.
#define ATHREADS 512
__global__ void __launch_bounds__(ATHREADS) k_attn() {
    __shared__ unsigned long long qm[TT][NN];
    __shared__ unsigned long long km[TT][NN];
    __shared__ unsigned long long vm[TT][NN];
    __shared__ unsigned int kT[TT][DD][7];
    __shared__ unsigned int vT[TT][DD][7];
    __shared__ __align__(16) unsigned int Gp[TT][DD][24];   // two u16 sums per word

    const int b = blockIdx.x, h = blockIdx.y;
    const int tid = threadIdx.x;

    // ---- pack spike bytes -> 48-bit masks (byte-gather multiply trick) ----
    for (int e = tid; e < 3*TT*NN; e += ATHREADS) {
        int ten = e / (TT*NN);
        int r = e - ten*(TT*NN);
        int t = r / NN, n = r - t*NN;
        int m = b*NN + n;
        const uint4* p = (const uint4*)(g_spk + ((size_t)t*MM + m)*DQKV + ten*CC + h*DD);
        unsigned long long mask = 0;
        #pragma unroll
        for (int q = 0; q < 3; q++) {
            uint4 u = p[q];
            unsigned n0 = (u.x * 0x01020408u) >> 24;
            unsigned n1 = (u.y * 0x01020408u) >> 24;
            unsigned n2 = (u.z * 0x01020408u) >> 24;
            unsigned n3 = (u.w * 0x01020408u) >> 24;
            unsigned hw = (n0 & 0xF) | ((n1 & 0xF) << 4) | ((n2 & 0xF) << 8) | ((n3 & 0xF) << 12);
            mask |= (unsigned long long)hw << (16*q);
        }
        if (ten == 0) qm[t][n] = mask;
        else if (ten == 1) km[t][n] = mask;
        else vm[t][n] = mask;
    }
    __syncthreads();

    // ---- bit-transpose k,v via warp ballot: 16 warps = 4 t x {k,v} x 2 g-halves ----
    {
        int w = tid >> 5, lane = tid & 31;
        int t = w >> 2;                 // 0..3
        int isv = (w >> 1) & 1;
        int half = w & 1;
        for (int g = half; g < 7; g += 2) {
            int m = g*32 + lane;
            unsigned long long mk = 0;
            if (m < NN) mk = isv ? vm[t][m] : km[t][m];
            #pragma unroll
            for (int j = 0; j < DD; j++) {
                unsigned bal = __ballot_sync(0xffffffffu, (unsigned)((mk >> j) & 1ull));
                if (lane == 0) { if (isv) vT[t][j][g] = bal; else kT[t][j][g] = bal; }
            }
        }
    }
    __syncthreads();

    // ---- Gp[t][j][p] = G[j][2p] | G[j][2p+1]<<16 via AND+popc ----
    for (int e = tid; e < TT*DD*24; e += ATHREADS) {
        int t = e / (DD*24), r = e - t*(DD*24);
        int j = r / 24, p = r - j*24;
        int s0 = 0, s1 = 0;
        #pragma unroll
        for (int g = 0; g < 7; g++) {
            s0 += __popc(kT[t][j][g] & vT[t][2*p][g]);
            s1 += __popc(kT[t][j][g] & vT[t][2*p + 1][g]);
        }
        Gp[t][j][p] = (unsigned)s0 | ((unsigned)s1 << 16);
    }
    __syncthreads();

    // ---- out[n, 8g..8g+7]: bit*word IMAD adds over j; LIF(0.5); write fp32 spikes ----
    for (int e = tid; e < 6*NN; e += ATHREADS) {
        int g = e / NN, n = e - g*NN;
        int p0 = g * 4;
        float v[8];
        #pragma unroll
        for (int d = 0; d < 8; d++) v[d] = 0.f;
        #pragma unroll
        for (int t = 0; t < TT; t++) {
            unsigned long long q = qm[t][n];
            unsigned ql = (unsigned)q, qh = (unsigned)(q >> 32);
            unsigned S[4] = {0u, 0u, 0u, 0u};
            #pragma unroll
            for (int j = 0; j < 32; j++) {
                unsigned bit = (ql >> j) & 1u;
                uint4 gw = *(const uint4*)&Gp[t][j][p0];
                S[0] += bit * gw.x; S[1] += bit * gw.y;
                S[2] += bit * gw.z; S[3] += bit * gw.w;
            }
            #pragma unroll
            for (int j = 0; j < 16; j++) {
                unsigned bit = (qh >> j) & 1u;
                uint4 gw = *(const uint4*)&Gp[t][32 + j][p0];
                S[0] += bit * gw.x; S[1] += bit * gw.y;
                S[2] += bit * gw.z; S[3] += bit * gw.w;
            }
            // [t][c][m] layout: c = h*DD + 8g + d, m = b*NN + n
            float* outp = &g_attnspk[((size_t)t*CC + h*DD + 8*g)*MM + b*NN + n];
            #pragma unroll
            for (int pp = 0; pp < 4; pp++) {
                int s0 = (int)(S[pp] & 0xFFFFu);
                int s1 = (int)(S[pp] >> 16);
                float x0 = (float)s0 * 0.125f;
                float x1 = (float)s1 * 0.125f;
                int d0i = 2*pp, d1i = 2*pp + 1;
                v[d0i] = __fadd_rn(v[d0i], __fmul_rn(__fadd_rn(x0, -v[d0i]), 0.5f));
                v[d1i] = __fadd_rn(v[d1i], __fmul_rn(__fadd_rn(x1, -v[d1i]), 0.5f));
                bool h0 = v[d0i] >= 0.5f, h1 = v[d1i] >= 0.5f;
                outp[(size_t)d0i * MM] = h0 ? 1.0f : 0.0f;
                outp[(size_t)d1i * MM] = h1 ? 1.0f : 0.0f;
                if (h0) v[d0i] = 0.f;
                if (h1) v[d1i] = 0.f;
            }
        }
    }
}

// ---------------- launch ----------------
extern "C" void kernel_launch(void* const* d_in, const int* in_sizes, int n_in,
                              void* d_out, int out_size) {
    const float* x  = (const float*)d_in[0];
    const float* wq = (const float*)d_in[1];
    const float* sq = (const float*)d_in[2];
    const float* bq = (const float*)d_in[3];
    const float* wk = (const float*)d_in[4];
    const float* sk = (const float*)d_in[5];
    const float* bk = (const float*)d_in[6];
    const float* wv = (const float*)d_in[7];
    const float* sv = (const float*)d_in[8];
    const float* bv = (const float*)d_in[9];
    const float* wp = (const float*)d_in[10];
    const float* sp = (const float*)d_in[11];
    const float* bp = (const float*)d_in[12];
    float* out = (float*)d_out;

    k_prepw<<<(CC*DQKV + CC*CC + 255)/256, 256>>>(wq, wk, wv, wp);
    k_prepx<<<(TT*CC*MM)/256, 256>>>(x);
    k_conv_lif<false><<<dim3(98, 18), 512>>>(sq, sk, sv, bq, bk, bv, nullptr);
    k_attn<<<dim3(BBATCH, HH), ATHREADS>>>();
    k_conv_lif<true><<<dim3(98, 6), 512>>>(sp, sp, sp, bp, bp, bp, out);
}

// round 16
// speedup vs baseline: 1.1423x; 1.1423x over previous
#include <cuda_runtime.h>
#include <cstdint>

#define TT 4
#define BBATCH 32
#define CC 384
#define NN 196
#define MM 6272            // BBATCH*NN
#define HH 8
#define DD 48
#define DQKV 1152

typedef unsigned long long u64;
typedef unsigned int u32;

// packed f32x2 helpers (sm_103a FFMA2 only reachable via PTX)
#define FMA_F32X2(d, a, b) \
    asm("fma.rn.f32x2 %0, %1, %2, %3;" : "=l"(d) : "l"(a), "l"(b), "l"(d))
#define DUP_F32X2(d, f) \
    asm("mov.b64 %0, {%1, %1};" : "=l"(d) : "r"(__float_as_uint(f)))
#define UNPACK_F32X2(lo, hi, v) \
    asm("mov.b64 {%0, %1}, %2;" : "=r"(lo), "=r"(hi) : "l"(v))

__device__ __forceinline__ void cpasync16(void* dst, const void* src) {
    unsigned ds = (unsigned)__cvta_generic_to_shared(dst);
    asm volatile("cp.async.cg.shared.global [%0], [%1], 16;" :: "r"(ds), "l"(src));
}
#define CP_COMMIT() asm volatile("cp.async.commit_group;" ::: "memory")
#define CP_WAIT1()  asm volatile("cp.async.wait_group 1;" ::: "memory")

// ---------------- scratch (device globals; no allocation allowed) ----------------
__device__ __align__(16) unsigned char g_spk[TT*MM*DQKV];   // spike bytes (q|k|v)
__device__ __align__(16) float g_attnspk[TT*CC*MM];         // attn-LIF spikes, [t][c][m]
__device__ __align__(16) float g_Wt1152[CC*DQKV];           // transposed qkv weights [C][1152]
__device__ __align__(16) float g_Wt384[CC*CC];              // transposed wp [C][384]

// ---------------- weight transpose prep ----------------
__global__ void k_prepw(const float* __restrict__ wq, const float* __restrict__ wk,
                        const float* __restrict__ wv, const float* __restrict__ wp) {
    int i = blockIdx.x * 256 + threadIdx.x;
    if (i < CC*DQKV) {
        int c = i / DQKV, dg = i - c*DQKV;
        int ten = dg / CC, d = dg - ten*CC;
        const float* w = (ten == 0) ? wq : (ten == 1) ? wk : wv;
        g_Wt1152[i] = w[d*CC + c];
    } else {
        int k = i - CC*DQKV;
        if (k < CC*CC) {
            int c = k / CC, d = k - c*CC;
            g_Wt384[k] = wp[d*CC + c];
        }
    }
}

// ---------------- fused conv(1x1) + BN + LIF GEMM (FFMA2, cp.async 2-stage) ----------------
// BM=64, BN=64, BK=16, 256 threads, 4x4 thread tile (two f32x2 m-pairs) x 4 t.
// conv<0> loads X DIRECTLY from its [t][b][c][n] layout: NN%4==0 means every 16B
// m-chunk stays inside one batch, so each loader thread's (b,n) decode is done once.
// Strict sequential k-order per accumulator -> bit-identical outputs.  (R14 tile)
template<bool FINAL>
__global__ void __launch_bounds__(256, 2) k_conv_lif(
    const float* __restrict__ X,
    const float* __restrict__ sc0, const float* __restrict__ sc1, const float* __restrict__ sc2,
    const float* __restrict__ bi0, const float* __restrict__ bi1, const float* __restrict__ bi2,
    float* __restrict__ outF)
{
    constexpr int DTOT = FINAL ? CC : DQKV;
    const float* __restrict__ Wt = FINAL ? g_Wt384 : g_Wt1152;
    constexpr size_t ASTRIDE = FINAL ? (size_t)MM : (size_t)NN;  // c-row stride in A source

    __shared__ __align__(16) float As[2][TT][16][64];   // 32 KB
    __shared__ __align__(16) float Ws[2][16][64];       //  8 KB

    const int tid = threadIdx.x;
    const int m0 = blockIdx.x * 64;
    const int d0 = blockIdx.y * 64;

    const int wr = tid >> 4;            // W row 0..15
    const int wch = (tid & 15) * 4;     // W col

    // per-thread A chunk bases (fixed (t,k,m-chunk) per i; advance by c0*ASTRIDE)
    const float* abase[4];
    #pragma unroll
    for (int i = 0; i < 4; i++) {
        int e = tid + i*256;
        int row = e >> 4;               // 0..63
        int t = row >> 4, k = row & 15;
        int mch = m0 + (e & 15) * 4;    // 4-aligned m; never crosses batch boundary
        if (FINAL) {
            abase[i] = g_attnspk + ((size_t)t*CC + k)*MM + mch;
        } else {
            int b = mch / NN, n = mch - b*NN;
            abase[i] = X + (((size_t)t*BBATCH + b)*CC + k)*NN + n;
        }
    }

    // acc2[t][pair][j]
    u64 acc2[TT][2][4];
    #pragma unroll
    for (int t = 0; t < TT; t++)
        #pragma unroll
        for (int p = 0; p < 2; p++)
            #pragma unroll
            for (int j = 0; j < 4; j++) acc2[t][p][j] = 0ull;

    // issue loads for a stage
    auto issue = [&](int slot, int c0) {
        #pragma unroll
        for (int i = 0; i < 4; i++) {
            int e = tid + i*256;
            int row = e >> 4;
            int t = row >> 4, k = row & 15;
            int ch = (e & 15) * 4;
            cpasync16(&As[slot][t][k][ch], abase[i] + (size_t)c0 * ASTRIDE);
        }
        cpasync16(&Ws[slot][wr][wch],
                  Wt + (size_t)(c0 + wr)*DTOT + d0 + wch);
    };

    // prologue: stages 0,1
    issue(0, 0);  CP_COMMIT();
    issue(1, 16); CP_COMMIT();

    const int tx4 = (tid & 15) * 4, ty4 = (tid >> 4) * 4;

    for (int kt = 0; kt < 24; kt++) {
        CP_WAIT1();
        __syncthreads();
        const int buf = kt & 1;
        #pragma unroll
        for (int k = 0; k < 16; k++) {
            float4 bfv = *(const float4*)&Ws[buf][k][tx4];
            u64 b2[4];
            DUP_F32X2(b2[0], bfv.x);
            DUP_F32X2(b2[1], bfv.y);
            DUP_F32X2(b2[2], bfv.z);
            DUP_F32X2(b2[3], bfv.w);
            #pragma unroll
            for (int t = 0; t < TT; t++) {
                ulonglong2 av = *(const ulonglong2*)&As[buf][t][k][ty4];
                #pragma unroll
                for (int j = 0; j < 4; j++) {
                    FMA_F32X2(acc2[t][0][j], av.x, b2[j]);
                    FMA_F32X2(acc2[t][1][j], av.y, b2[j]);
                }
            }
        }
        __syncthreads();
        if (kt + 2 < 24) issue(buf, (kt + 2) * 16);
        CP_COMMIT();
    }

    // unpack to scalar layout acc[t][i*4+j]
    float acc[TT][16];
    #pragma unroll
    for (int t = 0; t < TT; t++)
        #pragma unroll
        for (int p = 0; p < 2; p++)
            #pragma unroll
            for (int j = 0; j < 4; j++) {
                u32 lo, hi;
                UNPACK_F32X2(lo, hi, acc2[t][p][j]);
                acc[t][(2*p)*4 + j]     = __uint_as_float(lo);
                acc[t][(2*p + 1)*4 + j] = __uint_as_float(hi);
            }

    // ---- epilogue: BN + LIF (exact reference op sequence; no fma contraction) ----
    const int tx = tid & 15, ty = tid >> 4;
    int dl = d0 + tx*4;
    const float *sc, *bi;
    if (FINAL) { sc = sc0; bi = bi0; }
    else {
        int ten = d0 / CC;
        dl = d0 - ten*CC + tx*4;
        sc = (ten == 0) ? sc0 : (ten == 1) ? sc1 : sc2;
        bi = (ten == 0) ? bi0 : (ten == 1) ? bi1 : bi2;
    }
    float scv[4], biv[4];
    #pragma unroll
    for (int j = 0; j < 4; j++) { scv[j] = sc[dl + j]; biv[j] = bi[dl + j]; }

    if (!FINAL) {
        #pragma unroll
        for (int i = 0; i < 4; i++) {
            int m = m0 + ty*4 + i;
            float v[4] = {0.f, 0.f, 0.f, 0.f};
            #pragma unroll
            for (int t = 0; t < TT; t++) {
                unsigned pk = 0;
                #pragma unroll
                for (int j = 0; j < 4; j++) {
                    float y = __fadd_rn(__fmul_rn(acc[t][i*4 + j], scv[j]), biv[j]);
                    v[j] = __fadd_rn(v[j], __fmul_rn(__fadd_rn(y, -v[j]), 0.5f));
                    if (v[j] >= 1.0f) { pk |= 1u << (8*j); v[j] = 0.f; }
                }
                *(unsigned*)&g_spk[((size_t)t*MM + m)*DQKV + d0 + tx*4] = pk;
            }
        }
    } else {
        // NN % 4 == 0 -> the thread's 4 consecutive m never cross a batch boundary,
        // so each (t,j) writes one coalesced float4. Same per-(i,j,t) fp op sequence.
        const int mbase = m0 + ty*4;
        const int b_o = mbase / NN;
        const int n0 = mbase - b_o*NN;          // 4-aligned
        float v[4][4];
        #pragma unroll
        for (int i = 0; i < 4; i++)
            #pragma unroll
            for (int j = 0; j < 4; j++) v[i][j] = 0.f;
        #pragma unroll
        for (int t = 0; t < TT; t++) {
            #pragma unroll
            for (int j = 0; j < 4; j++) {
                float4 o;
                float* ov = &o.x;
                #pragma unroll
                for (int i = 0; i < 4; i++) {
                    float y = __fadd_rn(__fmul_rn(acc[t][i*4 + j], scv[j]), biv[j]);
                    v[i][j] = __fadd_rn(v[i][j], __fmul_rn(__fadd_rn(y, -v[i][j]), 0.5f));
                    bool hh = v[i][j] >= 1.0f;
                    ov[i] = hh ? 1.0f : 0.0f;
                    if (hh) v[i][j] = 0.f;
                }
                *(float4*)&outF[(((size_t)t*BBATCH + b_o)*CC + (dl + j))*NN + n0] = o;
            }
        }
    }
}

// ---------------- attention (pack fused, 512 threads): out = q @ (k^T v) * 0.125, LIF(0.5) ----
// Integer-exact: spikes binary, G entries <=196, sums <=9408 < 2^16.
// Phase 4 uses bit*word IMADs (fma pipe) to balance against the alu pipe.
// Output written in [t][c][m] layout for the projection conv.
#define ATHREADS 512
__global__ void __launch_bounds__(ATHREADS) k_attn() {
    __shared__ unsigned long long qm[TT][NN];
    __shared__ unsigned long long km[TT][NN];
    __shared__ unsigned long long vm[TT][NN];
    __shared__ unsigned int kT[TT][DD][7];
    __shared__ unsigned int vT[TT][DD][7];
    __shared__ __align__(16) unsigned int Gp[TT][DD][24];   // two u16 sums per word

    const int b = blockIdx.x, h = blockIdx.y;
    const int tid = threadIdx.x;

    // ---- pack spike bytes -> 48-bit masks (byte-gather multiply trick) ----
    for (int e = tid; e < 3*TT*NN; e += ATHREADS) {
        int ten = e / (TT*NN);
        int r = e - ten*(TT*NN);
        int t = r / NN, n = r - t*NN;
        int m = b*NN + n;
        const uint4* p = (const uint4*)(g_spk + ((size_t)t*MM + m)*DQKV + ten*CC + h*DD);
        unsigned long long mask = 0;
        #pragma unroll
        for (int q = 0; q < 3; q++) {
            uint4 u = p[q];
            unsigned n0 = (u.x * 0x01020408u) >> 24;
            unsigned n1 = (u.y * 0x01020408u) >> 24;
            unsigned n2 = (u.z * 0x01020408u) >> 24;
            unsigned n3 = (u.w * 0x01020408u) >> 24;
            unsigned hw = (n0 & 0xF) | ((n1 & 0xF) << 4) | ((n2 & 0xF) << 8) | ((n3 & 0xF) << 12);
            mask |= (unsigned long long)hw << (16*q);
        }
        if (ten == 0) qm[t][n] = mask;
        else if (ten == 1) km[t][n] = mask;
        else vm[t][n] = mask;
    }
    __syncthreads();

    // ---- bit-transpose k,v via warp ballot: 16 warps = 4 t x {k,v} x 2 g-halves ----
    {
        int w = tid >> 5, lane = tid & 31;
        int t = w >> 2;                 // 0..3
        int isv = (w >> 1) & 1;
        int half = w & 1;
        for (int g = half; g < 7; g += 2) {
            int m = g*32 + lane;
            unsigned long long mk = 0;
            if (m < NN) mk = isv ? vm[t][m] : km[t][m];
            #pragma unroll
            for (int j = 0; j < DD; j++) {
                unsigned bal = __ballot_sync(0xffffffffu, (unsigned)((mk >> j) & 1ull));
                if (lane == 0) { if (isv) vT[t][j][g] = bal; else kT[t][j][g] = bal; }
            }
        }
    }
    __syncthreads();

    // ---- Gp[t][j][p] = G[j][2p] | G[j][2p+1]<<16 via AND+popc ----
    for (int e = tid; e < TT*DD*24; e += ATHREADS) {
        int t = e / (DD*24), r = e - t*(DD*24);
        int j = r / 24, p = r - j*24;
        int s0 = 0, s1 = 0;
        #pragma unroll
        for (int g = 0; g < 7; g++) {
            s0 += __popc(kT[t][j][g] & vT[t][2*p][g]);
            s1 += __popc(kT[t][j][g] & vT[t][2*p + 1][g]);
        }
        Gp[t][j][p] = (unsigned)s0 | ((unsigned)s1 << 16);
    }
    __syncthreads();

    // ---- out[n, 8g..8g+7]: bit*word IMAD adds over j; LIF(0.5); write fp32 spikes ----
    for (int e = tid; e < 6*NN; e += ATHREADS) {
        int g = e / NN, n = e - g*NN;
        int p0 = g * 4;
        float v[8];
        #pragma unroll
        for (int d = 0; d < 8; d++) v[d] = 0.f;
        #pragma unroll
        for (int t = 0; t < TT; t++) {
            unsigned long long q = qm[t][n];
            unsigned ql = (unsigned)q, qh = (unsigned)(q >> 32);
            unsigned S[4] = {0u, 0u, 0u, 0u};
            #pragma unroll
            for (int j = 0; j < 32; j++) {
                unsigned bit = (ql >> j) & 1u;
                uint4 gw = *(const uint4*)&Gp[t][j][p0];
                S[0] += bit * gw.x; S[1] += bit * gw.y;
                S[2] += bit * gw.z; S[3] += bit * gw.w;
            }
            #pragma unroll
            for (int j = 0; j < 16; j++) {
                unsigned bit = (qh >> j) & 1u;
                uint4 gw = *(const uint4*)&Gp[t][32 + j][p0];
                S[0] += bit * gw.x; S[1] += bit * gw.y;
                S[2] += bit * gw.z; S[3] += bit * gw.w;
            }
            // [t][c][m] layout: c = h*DD + 8g + d, m = b*NN + n
            float* outp = &g_attnspk[((size_t)t*CC + h*DD + 8*g)*MM + b*NN + n];
            #pragma unroll
            for (int pp = 0; pp < 4; pp++) {
                int s0 = (int)(S[pp] & 0xFFFFu);
                int s1 = (int)(S[pp] >> 16);
                float x0 = (float)s0 * 0.125f;
                float x1 = (float)s1 * 0.125f;
                int d0i = 2*pp, d1i = 2*pp + 1;
                v[d0i] = __fadd_rn(v[d0i], __fmul_rn(__fadd_rn(x0, -v[d0i]), 0.5f));
                v[d1i] = __fadd_rn(v[d1i], __fmul_rn(__fadd_rn(x1, -v[d1i]), 0.5f));
                bool h0 = v[d0i] >= 0.5f, h1 = v[d1i] >= 0.5f;
                outp[(size_t)d0i * MM] = h0 ? 1.0f : 0.0f;
                outp[(size_t)d1i * MM] = h1 ? 1.0f : 0.0f;
                if (h0) v[d0i] = 0.f;
                if (h1) v[d1i] = 0.f;
            }
        }
    }
}

// ---------------- launch ----------------
extern "C" void kernel_launch(void* const* d_in, const int* in_sizes, int n_in,
                              void* d_out, int out_size) {
    const float* x  = (const float*)d_in[0];
    const float* wq = (const float*)d_in[1];
    const float* sq = (const float*)d_in[2];
    const float* bq = (const float*)d_in[3];
    const float* wk = (const float*)d_in[4];
    const float* sk = (const float*)d_in[5];
    const float* bk = (const float*)d_in[6];
    const float* wv = (const float*)d_in[7];
    const float* sv = (const float*)d_in[8];
    const float* bv = (const float*)d_in[9];
    const float* wp = (const float*)d_in[10];
    const float* sp = (const float*)d_in[11];
    const float* bp = (const float*)d_in[12];
    float* out = (float*)d_out;

    k_prepw<<<(CC*DQKV + CC*CC + 255)/256, 256>>>(wq, wk, wv, wp);
    k_conv_lif<false><<<dim3(98, 18), 256>>>(x, sq, sk, sv, bq, bk, bv, nullptr);
    k_attn<<<dim3(BBATCH, HH), ATHREADS>>>();
    k_conv_lif<true><<<dim3(98, 6), 256>>>(x, sp, sp, sp, bp, bp, bp, out);
}